// round 3
// baseline (speedup 1.0000x reference)
#include <cuda_runtime.h>
#include <cstdint>

#define BB 4
#define DD 512
#define NN 1536
#define HH 8
#define DH 64          // per-head dim

// ---------------- scratch (device globals; no allocation allowed) ----------
__device__ float g_q[(size_t)BB * HH * DH * NN];   // [b,h,d,n]
__device__ float g_k[(size_t)BB * HH * DH * NN];   // [b,h,d,n]
__device__ float g_v[(size_t)BB * HH * DH * NN];   // [b,h,d,n]  (same layout as Q/K)
__device__ float g_s[(size_t)BB * HH * NN * NN];   // scores -> probs, [b,h,n,m]
__device__ float g_x[(size_t)BB * DD * NN];        // [b,c,n]
__device__ unsigned char g_mask[(size_t)NN * NN];  // canonical 0/1 mask
__device__ unsigned g_minenc;
__device__ unsigned g_maskflags;

// order-preserving float <-> uint encoding
__device__ __forceinline__ unsigned enc_f(float x) {
    unsigned b = __float_as_uint(x);
    return (b & 0x80000000u) ? ~b : (b | 0x80000000u);
}
__device__ __forceinline__ float dec_f(unsigned e) {
    return (e & 0x80000000u) ? __uint_as_float(e ^ 0x80000000u)
                             : __uint_as_float(~e);
}

__global__ void init_kernel() { g_minenc = 0xFFFFFFFFu; g_maskflags = 0u; }

// ---------------- mask dtype classification + normalization ----------------
__global__ void __launch_bounds__(256)
mask_classify_kernel(const unsigned* __restrict__ mw) {
    const int total = NN * NN / 4;
    unsigned local = 0;
    for (int i = blockIdx.x * 256 + threadIdx.x; i < total; i += gridDim.x * 256) {
        unsigned w = mw[i];
        if (w != 0u && w != 1u)          local |= 1u;
        if (w != 0u && w != 0x3f800000u) local |= 2u;
    }
#pragma unroll
    for (int o = 16; o > 0; o >>= 1) local |= __shfl_xor_sync(0xffffffffu, local, o);
    if ((threadIdx.x & 31) == 0 && local) atomicOr(&g_maskflags, local);
}

__global__ void __launch_bounds__(256)
mask_convert_kernel(const void* __restrict__ mraw) {
    const unsigned f = g_maskflags;
    const int mode = ((f & 2u) == 0u) ? 2 : (((f & 1u) == 0u) ? 1 : 0);
    const int total = NN * NN;
    if (mode == 0) {
        const unsigned char* m8 = (const unsigned char*)mraw;
        for (int i = blockIdx.x * 256 + threadIdx.x; i < total; i += gridDim.x * 256)
            g_mask[i] = m8[i] ? 1 : 0;
    } else if (mode == 1) {
        const int* mi = (const int*)mraw;
        for (int i = blockIdx.x * 256 + threadIdx.x; i < total; i += gridDim.x * 256)
            g_mask[i] = mi[i] ? 1 : 0;
    } else {
        const float* mf = (const float*)mraw;
        for (int i = blockIdx.x * 256 + threadIdx.x; i < total; i += gridDim.x * 256)
            g_mask[i] = (mf[i] != 0.0f) ? 1 : 0;
    }
}

// ---------------- projection: Y[b,o,n] = sum_c W[o,c] X[b,c,n] + bias[o] ----
// 64(o) x 128(n) tile, 128 threads, 8x8 per thread, k-step 16, double buffered
// MODE 0: plain [b,o,n]; MODE 1: head [b,h,d,n]
template <int MODE>
__global__ void __launch_bounds__(128)
proj_kernel(const float* __restrict__ X, const float* __restrict__ W,
            const float* __restrict__ bias, float* __restrict__ Y) {
    __shared__ float sA[2][16][64];   // [buf][c][o]
    __shared__ float sB[2][16][128];  // [buf][c][n]
    const int b  = blockIdx.z;
    const int o0 = blockIdx.y * 64;
    const int n0 = blockIdx.x * 128;
    const int t  = threadIdx.x;
    const int tx = t & 15, ty = t >> 4;           // tx: n group, ty: o group
    const float* Xb = X + (size_t)b * DD * NN;

    const int aro = t >> 1, ac0 = (t & 1) * 8;    // A load: o row, c offset
    const int brc = t >> 3, bn0 = (t & 7) * 16;   // B load: c row, n offset

    float4 pa0, pa1, pb0, pb1, pb2, pb3;
    const float* wrow = &W[(size_t)(o0 + aro) * DD];
    pa0 = *(const float4*)&wrow[ac0];
    pa1 = *(const float4*)&wrow[ac0 + 4];
    pb0 = *(const float4*)&Xb[(size_t)brc * NN + n0 + bn0];
    pb1 = *(const float4*)&Xb[(size_t)brc * NN + n0 + bn0 + 4];
    pb2 = *(const float4*)&Xb[(size_t)brc * NN + n0 + bn0 + 8];
    pb3 = *(const float4*)&Xb[(size_t)brc * NN + n0 + bn0 + 12];
    sA[0][ac0 + 0][aro] = pa0.x; sA[0][ac0 + 1][aro] = pa0.y;
    sA[0][ac0 + 2][aro] = pa0.z; sA[0][ac0 + 3][aro] = pa0.w;
    sA[0][ac0 + 4][aro] = pa1.x; sA[0][ac0 + 5][aro] = pa1.y;
    sA[0][ac0 + 6][aro] = pa1.z; sA[0][ac0 + 7][aro] = pa1.w;
    *(float4*)&sB[0][brc][bn0 + 0]  = pb0;
    *(float4*)&sB[0][brc][bn0 + 4]  = pb1;
    *(float4*)&sB[0][brc][bn0 + 8]  = pb2;
    *(float4*)&sB[0][brc][bn0 + 12] = pb3;
    __syncthreads();

    float acc[8][8] = {};
    const int NK = DD / 16;
    for (int kt = 0; kt < NK; kt++) {
        const int cur = kt & 1;
        if (kt + 1 < NK) {
            const int c0 = (kt + 1) * 16;
            pa0 = *(const float4*)&wrow[c0 + ac0];
            pa1 = *(const float4*)&wrow[c0 + ac0 + 4];
            pb0 = *(const float4*)&Xb[(size_t)(c0 + brc) * NN + n0 + bn0];
            pb1 = *(const float4*)&Xb[(size_t)(c0 + brc) * NN + n0 + bn0 + 4];
            pb2 = *(const float4*)&Xb[(size_t)(c0 + brc) * NN + n0 + bn0 + 8];
            pb3 = *(const float4*)&Xb[(size_t)(c0 + brc) * NN + n0 + bn0 + 12];
        }
#pragma unroll
        for (int k = 0; k < 16; k++) {
            float a[8], bb[8];
            *(float4*)&a[0]  = *(const float4*)&sA[cur][k][ty * 8];
            *(float4*)&a[4]  = *(const float4*)&sA[cur][k][ty * 8 + 4];
            *(float4*)&bb[0] = *(const float4*)&sB[cur][k][tx * 8];
            *(float4*)&bb[4] = *(const float4*)&sB[cur][k][tx * 8 + 4];
#pragma unroll
            for (int i = 0; i < 8; i++)
#pragma unroll
                for (int j = 0; j < 8; j++) acc[i][j] += a[i] * bb[j];
        }
        if (kt + 1 < NK) {
            const int nx = cur ^ 1;
            sA[nx][ac0 + 0][aro] = pa0.x; sA[nx][ac0 + 1][aro] = pa0.y;
            sA[nx][ac0 + 2][aro] = pa0.z; sA[nx][ac0 + 3][aro] = pa0.w;
            sA[nx][ac0 + 4][aro] = pa1.x; sA[nx][ac0 + 5][aro] = pa1.y;
            sA[nx][ac0 + 6][aro] = pa1.z; sA[nx][ac0 + 7][aro] = pa1.w;
            *(float4*)&sB[nx][brc][bn0 + 0]  = pb0;
            *(float4*)&sB[nx][brc][bn0 + 4]  = pb1;
            *(float4*)&sB[nx][brc][bn0 + 8]  = pb2;
            *(float4*)&sB[nx][brc][bn0 + 12] = pb3;
        }
        __syncthreads();
    }

#pragma unroll
    for (int i = 0; i < 8; i++) {
        const int o = o0 + ty * 8 + i;
        const float bo = bias[o];
        float4 r0 = make_float4(acc[i][0] + bo, acc[i][1] + bo, acc[i][2] + bo, acc[i][3] + bo);
        float4 r1 = make_float4(acc[i][4] + bo, acc[i][5] + bo, acc[i][6] + bo, acc[i][7] + bo);
        if (MODE == 0) {
            float* p = &Y[((size_t)b * DD + o) * NN + n0 + tx * 8];
            *(float4*)&p[0] = r0; *(float4*)&p[4] = r1;
        } else {
            const int h = o & 7, dd = o >> 3;
            float* p = &Y[(((size_t)b * HH + h) * DH + dd) * NN + n0 + tx * 8];
            *(float4*)&p[0] = r0; *(float4*)&p[4] = r1;
        }
    }
}

// ---------------- scores: S[bh,n,m] = (1/8) sum_d Q[bh,d,n] K[bh,d,m] -------
// 128x128 tile, 256 threads, 8x8 per thread, k-step 16 double buffered (K=64)
__global__ void __launch_bounds__(256)
scores_kernel() {
    __shared__ float sQ[2][16][128];  // [buf][d][n]
    __shared__ float sK[2][16][128];  // [buf][d][m]
    __shared__ float sred[8];
    const int bh = blockIdx.z;
    const int n0 = blockIdx.y * 128;
    const int m0 = blockIdx.x * 128;
    const int t  = threadIdx.x;
    const int tx = t & 15, ty = t >> 4;
    const float* Q = g_q + (size_t)bh * DH * NN;
    const float* K = g_k + (size_t)bh * DH * NN;

    const int lr = t >> 4, lc = (t & 15) * 8;  // load: d row (0..15), col offset

    float4 q0, q1, k0, k1;
    q0 = *(const float4*)&Q[(size_t)lr * NN + n0 + lc];
    q1 = *(const float4*)&Q[(size_t)lr * NN + n0 + lc + 4];
    k0 = *(const float4*)&K[(size_t)lr * NN + m0 + lc];
    k1 = *(const float4*)&K[(size_t)lr * NN + m0 + lc + 4];
    *(float4*)&sQ[0][lr][lc]     = q0;
    *(float4*)&sQ[0][lr][lc + 4] = q1;
    *(float4*)&sK[0][lr][lc]     = k0;
    *(float4*)&sK[0][lr][lc + 4] = k1;
    __syncthreads();

    float acc[8][8] = {};
    const int NK = DH / 16;  // 4
    for (int kt = 0; kt < NK; kt++) {
        const int cur = kt & 1;
        if (kt + 1 < NK) {
            const int d0 = (kt + 1) * 16;
            q0 = *(const float4*)&Q[(size_t)(d0 + lr) * NN + n0 + lc];
            q1 = *(const float4*)&Q[(size_t)(d0 + lr) * NN + n0 + lc + 4];
            k0 = *(const float4*)&K[(size_t)(d0 + lr) * NN + m0 + lc];
            k1 = *(const float4*)&K[(size_t)(d0 + lr) * NN + m0 + lc + 4];
        }
#pragma unroll
        for (int k = 0; k < 16; k++) {
            float a[8], bb[8];
            *(float4*)&a[0]  = *(const float4*)&sQ[cur][k][ty * 8];
            *(float4*)&a[4]  = *(const float4*)&sQ[cur][k][ty * 8 + 4];
            *(float4*)&bb[0] = *(const float4*)&sK[cur][k][tx * 8];
            *(float4*)&bb[4] = *(const float4*)&sK[cur][k][tx * 8 + 4];
#pragma unroll
            for (int i = 0; i < 8; i++)
#pragma unroll
                for (int j = 0; j < 8; j++) acc[i][j] += a[i] * bb[j];
        }
        if (kt + 1 < NK) {
            const int nx = cur ^ 1;
            *(float4*)&sQ[nx][lr][lc]     = q0;
            *(float4*)&sQ[nx][lr][lc + 4] = q1;
            *(float4*)&sK[nx][lr][lc]     = k0;
            *(float4*)&sK[nx][lr][lc + 4] = k1;
        }
        __syncthreads();
    }

    float mn = __int_as_float(0x7f800000);
#pragma unroll
    for (int i = 0; i < 8; i++) {
        const int n = n0 + ty * 8 + i;
        float4 r0 = make_float4(acc[i][0] * 0.125f, acc[i][1] * 0.125f,
                                acc[i][2] * 0.125f, acc[i][3] * 0.125f);
        float4 r1 = make_float4(acc[i][4] * 0.125f, acc[i][5] * 0.125f,
                                acc[i][6] * 0.125f, acc[i][7] * 0.125f);
        mn = fminf(mn, fminf(fminf(r0.x, r0.y), fminf(r0.z, r0.w)));
        mn = fminf(mn, fminf(fminf(r1.x, r1.y), fminf(r1.z, r1.w)));
        float* p = &g_s[((size_t)bh * NN + n) * NN + m0 + tx * 8];
        *(float4*)&p[0] = r0; *(float4*)&p[4] = r1;
    }
#pragma unroll
    for (int o = 16; o > 0; o >>= 1) mn = fminf(mn, __shfl_xor_sync(0xffffffffu, mn, o));
    if ((t & 31) == 0) sred[t >> 5] = mn;
    __syncthreads();
    if (t == 0) {
        float v = sred[0];
#pragma unroll
        for (int i = 1; i < 8; i++) v = fminf(v, sred[i]);
        atomicMin(&g_minenc, enc_f(v));
    }
}

// ---------------- output 2: mean over heads of masked scores ----------------
__global__ void __launch_bounds__(256)
out2_kernel(float* __restrict__ O2) {
    const int idx = blockIdx.x * 256 + threadIdx.x;
    const int total = BB * NN * NN / 4;
    if (idx >= total) return;
    const int e = idx * 4;
    const int m = e % NN;
    const int n = (e / NN) % NN;
    const int b = e / (NN * NN);

    float4 acc = make_float4(0.f, 0.f, 0.f, 0.f);
#pragma unroll
    for (int h = 0; h < HH; h++) {
        float4 s = *(const float4*)&g_s[((size_t)(b * HH + h) * NN + n) * NN + m];
        acc.x += s.x; acc.y += s.y; acc.z += s.z; acc.w += s.w;
    }
    const float pen = dec_f(g_minenc) - 20.0f;
    uchar4 mk = *(const uchar4*)&g_mask[(size_t)n * NN + m];
    acc.x = acc.x * 0.125f + (mk.x ? 0.f : pen);
    acc.y = acc.y * 0.125f + (mk.y ? 0.f : pen);
    acc.z = acc.z * 0.125f + (mk.z ? 0.f : pen);
    acc.w = acc.w * 0.125f + (mk.w ? 0.f : pen);
    *(float4*)&O2[e] = acc;
}

// ---------------- softmax (in place, scores -> probs) -----------------------
__global__ void __launch_bounds__(256)
softmax_kernel() {
    const int row = blockIdx.x;               // bh*NN + n
    const int n   = row % NN;
    float* S = g_s + (size_t)row * NN;
    const unsigned char* mrow = g_mask + (size_t)n * NN;
    const int tid = threadIdx.x;
    const float pen = dec_f(g_minenc) - 20.0f;

    __shared__ float sredA[8];
    __shared__ float sredB[8];

    float v[6];
    float mx = __int_as_float(0xff800000);
#pragma unroll
    for (int i = 0; i < 6; i++) {
        int m = tid + i * 256;
        float s = S[m];
        if (!mrow[m]) s += pen;
        v[i] = s;
        mx = fmaxf(mx, s);
    }
#pragma unroll
    for (int o = 16; o > 0; o >>= 1) mx = fmaxf(mx, __shfl_xor_sync(0xffffffffu, mx, o));
    if ((tid & 31) == 0) sredA[tid >> 5] = mx;
    __syncthreads();
    mx = sredA[0];
#pragma unroll
    for (int i = 1; i < 8; i++) mx = fmaxf(mx, sredA[i]);

    float sum = 0.f;
#pragma unroll
    for (int i = 0; i < 6; i++) {
        v[i] = __expf(v[i] - mx);
        sum += v[i];
    }
#pragma unroll
    for (int o = 16; o > 0; o >>= 1) sum += __shfl_xor_sync(0xffffffffu, sum, o);
    if ((tid & 31) == 0) sredB[tid >> 5] = sum;
    __syncthreads();
    sum = sredB[0];
#pragma unroll
    for (int i = 1; i < 8; i++) sum += sredB[i];
    const float inv = 1.0f / sum;
#pragma unroll
    for (int i = 0; i < 6; i++) S[tid + i * 256] = v[i] * inv;
}

// ---------------- PV: X[n,d] = sum_m P[n,m] V[d,m] -> g_x[b, d*8+h, n] ------
// 128(n) x 64(d) tile, 128 threads, 8x8 per thread, m-step 16 double buffered
__global__ void __launch_bounds__(128)
pv_kernel() {
    __shared__ float sP[2][16][128];  // [buf][m][n]
    __shared__ float sV[2][16][64];   // [buf][m][d]
    const int bh = blockIdx.y;
    const int n0 = blockIdx.x * 128;
    const int t  = threadIdx.x;
    const int tx = t & 7, ty = t >> 3;            // tx: d group (0..7), ty: n group (0..15)
    const float* P = g_s + (size_t)bh * NN * NN;
    const float* V = g_v + (size_t)bh * DH * NN;  // [d][m]

    const int vd = t >> 1, vm0 = (t & 1) * 8;     // V load map

    float pr[16];      // P prefetch: 16 contiguous floats of row n0+t
    float4 v0, v1;     // V prefetch
    {
        const float* prow = &P[(size_t)(n0 + t) * NN];
        *(float4*)&pr[0]  = *(const float4*)&prow[0];
        *(float4*)&pr[4]  = *(const float4*)&prow[4];
        *(float4*)&pr[8]  = *(const float4*)&prow[8];
        *(float4*)&pr[12] = *(const float4*)&prow[12];
        v0 = *(const float4*)&V[(size_t)vd * NN + vm0];
        v1 = *(const float4*)&V[(size_t)vd * NN + vm0 + 4];
    }
#pragma unroll
    for (int mi = 0; mi < 16; mi++) sP[0][mi][t] = pr[mi];
    sV[0][vm0 + 0][vd] = v0.x; sV[0][vm0 + 1][vd] = v0.y;
    sV[0][vm0 + 2][vd] = v0.z; sV[0][vm0 + 3][vd] = v0.w;
    sV[0][vm0 + 4][vd] = v1.x; sV[0][vm0 + 5][vd] = v1.y;
    sV[0][vm0 + 6][vd] = v1.z; sV[0][vm0 + 7][vd] = v1.w;
    __syncthreads();

    float acc[8][8] = {};
    const int NK = NN / 16;  // 96
    for (int mt = 0; mt < NK; mt++) {
        const int cur = mt & 1;
        if (mt + 1 < NK) {
            const int m0 = (mt + 1) * 16;
            const float* prow = &P[(size_t)(n0 + t) * NN + m0];
            *(float4*)&pr[0]  = *(const float4*)&prow[0];
            *(float4*)&pr[4]  = *(const float4*)&prow[4];
            *(float4*)&pr[8]  = *(const float4*)&prow[8];
            *(float4*)&pr[12] = *(const float4*)&prow[12];
            v0 = *(const float4*)&V[(size_t)vd * NN + m0 + vm0];
            v1 = *(const float4*)&V[(size_t)vd * NN + m0 + vm0 + 4];
        }
#pragma unroll
        for (int m = 0; m < 16; m++) {
            float a[8], bb[8];
            *(float4*)&a[0]  = *(const float4*)&sP[cur][m][ty * 8];
            *(float4*)&a[4]  = *(const float4*)&sP[cur][m][ty * 8 + 4];
            *(float4*)&bb[0] = *(const float4*)&sV[cur][m][tx * 8];
            *(float4*)&bb[4] = *(const float4*)&sV[cur][m][tx * 8 + 4];
#pragma unroll
            for (int i = 0; i < 8; i++)
#pragma unroll
                for (int j = 0; j < 8; j++) acc[i][j] += a[i] * bb[j];
        }
        if (mt + 1 < NK) {
            const int nx = cur ^ 1;
#pragma unroll
            for (int mi = 0; mi < 16; mi++) sP[nx][mi][t] = pr[mi];
            sV[nx][vm0 + 0][vd] = v0.x; sV[nx][vm0 + 1][vd] = v0.y;
            sV[nx][vm0 + 2][vd] = v0.z; sV[nx][vm0 + 3][vd] = v0.w;
            sV[nx][vm0 + 4][vd] = v1.x; sV[nx][vm0 + 5][vd] = v1.y;
            sV[nx][vm0 + 6][vd] = v1.z; sV[nx][vm0 + 7][vd] = v1.w;
        }
        __syncthreads();
    }

    const int b = bh >> 3, h = bh & 7;
#pragma unroll
    for (int j = 0; j < 8; j++) {
        const int d = tx * 8 + j;
        const int c = d * 8 + h;
        float* p = &g_x[((size_t)b * DD + c) * NN + n0 + ty * 8];
        *(float4*)&p[0] = make_float4(acc[0][j], acc[1][j], acc[2][j], acc[3][j]);
        *(float4*)&p[4] = make_float4(acc[4][j], acc[5][j], acc[6][j], acc[7][j]);
    }
}

// ---------------- launch ----------------------------------------------------
extern "C" void kernel_launch(void* const* d_in, const int* in_sizes, int n_in,
                              void* d_out, int out_size) {
    const float* query = (const float*)d_in[0];
    const float* key   = (const float*)d_in[1];
    const float* value = (const float*)d_in[2];
    // d_in[3] = dist (unused)
    const void* mask   = d_in[4];
    const float* Wq = (const float*)d_in[5];
    const float* bq = (const float*)d_in[6];
    const float* Wk = (const float*)d_in[7];
    const float* bk = (const float*)d_in[8];
    const float* Wv = (const float*)d_in[9];
    const float* bv = (const float*)d_in[10];
    const float* Wm = (const float*)d_in[11];
    const float* bm = (const float*)d_in[12];

    float* out  = (float*)d_out;                         // [B, D, N]
    float* out2 = out + (size_t)BB * DD * NN;            // [B, N, N]

    float *pq, *pk, *pv, *px;
    cudaGetSymbolAddress((void**)&pq, g_q);
    cudaGetSymbolAddress((void**)&pk, g_k);
    cudaGetSymbolAddress((void**)&pv, g_v);
    cudaGetSymbolAddress((void**)&px, g_x);

    init_kernel<<<1, 1>>>();

    mask_classify_kernel<<<256, 256>>>((const unsigned*)mask);
    mask_convert_kernel<<<256, 256>>>(mask);

    dim3 gproj(NN / 128, DD / 64, BB);   // 12 x 8 x 4
    proj_kernel<1><<<gproj, 128>>>(query, Wq, bq, pq);
    proj_kernel<1><<<gproj, 128>>>(key,   Wk, bk, pk);
    proj_kernel<1><<<gproj, 128>>>(value, Wv, bv, pv);

    scores_kernel<<<dim3(NN / 128, NN / 128, BB * HH), 256>>>();

    {
        int total4 = BB * NN * NN / 4;
        out2_kernel<<<(total4 + 255) / 256, 256>>>(out2);
    }

    softmax_kernel<<<BB * HH * NN, 256>>>();

    pv_kernel<<<dim3(NN / 128, BB * HH), 128>>>();

    proj_kernel<0><<<gproj, 128>>>(px, Wm, bm, out);
}